// round 12
// baseline (speedup 1.0000x reference)
#include <cuda_runtime.h>
#include <math.h>

#define N_EDGES 100000
#define N_ATOMS 10000
#define UNC_W   1280   // sum over l of 3^l * 32 = 32+96+288+864
#define CAT_W   960

// uncoupled-space per-atom features and pooled target (both ~51.2MB, L2-resident)
__device__ __align__(16) float g_uncF[(size_t)N_ATOMS * UNC_W];
__device__ __align__(16) float g_pool[(size_t)N_ATOMS * UNC_W];
// cat scratch reuses g_uncF (k_pool finishes reading it before k_couple writes)
#define g_cat g_uncF

// edge counting-sort scratch
__device__ int g_cnt[N_ATOMS];
__device__ int g_off[N_ATOMS + 1];
__device__ int g_cur[N_ATOMS];
__device__ int g_eid[N_EDGES];

// ---------------------------------------------------------------------------
__device__ __forceinline__ int sel4(int l, int a, int b, int c, int d) {
    return l == 0 ? a : (l == 1 ? b : (l == 2 ? c : d));
}
__device__ __forceinline__ const float* selp(int l, const float* a, const float* b,
                                             const float* c, const float* d) {
    return l == 0 ? a : (l == 1 ? b : (l == 2 ? c : d));
}

// ---------------------------------------------------------------------------
// K_uncF: per-atom uncouple of features (+ fused zeroing of g_cnt).
// unc_f[l][d,k] = sum_{lp<=l} sum_m U_l[d, lp^2+m] * feat_lp[n, m, lo_l + k]
// layout: g_uncF[n*1280 + F_OFF[l] + d*32 + k], F_OFF={0,32,128,416}
// ---------------------------------------------------------------------------
__global__ __launch_bounds__(128) void k_uncf(
    const float* __restrict__ f0, const float* __restrict__ f1,
    const float* __restrict__ f2, const float* __restrict__ f3,
    const float* __restrict__ U0, const float* __restrict__ U1,
    const float* __restrict__ U2, const float* __restrict__ U3)
{
    __shared__ float fb[CAT_W];  // feat rows of this atom: offsets {0,128,416,736}
    const int n = blockIdx.x;
    const int t = threadIdx.x;

    if (t == 0) g_cnt[n] = 0;    // fused counting-sort init

    for (int u = t; u < 240; u += 128) {
        int l    = (u >= 184) ? 3 : (u >= 104) ? 2 : (u >= 32) ? 1 : 0;
        int off4 = u - sel4(l, 0, 32, 104, 184);
        int row  = sel4(l, 128, 288, 320, 224);
        const float* src = selp(l, f0, f1, f2, f3) + (size_t)n * row;
        float4 v = __ldg(reinterpret_cast<const float4*>(src + off4 * 4));
        *reinterpret_cast<float4*>(&fb[sel4(l, 0, 128, 416, 736) + off4 * 4]) = v;
    }
    __syncthreads();

    float* dst = g_uncF + (size_t)n * UNC_W;
    for (int v = t; v < UNC_W; v += 128) {
        int l   = (v >= 416) ? 3 : (v >= 128) ? 2 : (v >= 32) ? 1 : 0;
        int idx = v - sel4(l, 0, 32, 128, 416);
        int d   = idx >> 5;
        int k   = idx & 31;
        int lo  = sel4(l, 96, 64, 32, 0);
        const float* Ul = selp(l, U0, U1, U2, U3);
        int L1 = (l + 1) * (l + 1);
        float acc = 0.f;
        #pragma unroll
        for (int lp = 0; lp <= 3; lp++) {
            if (lp > l) break;
            int fboff = sel4(lp, 0, 128, 416, 736);
            int w     = sel4(lp, 128, 96, 64, 32);
            int ub    = 2 * lp + 1;
            int ubase = d * L1 + lp * lp;
            for (int m = 0; m < ub; m++)
                acc += __ldg(&Ul[ubase + m]) * fb[fboff + m * w + lo + k];
        }
        dst[v] = acc;
    }
}

// ---------------------------------------------------------------------------
// Counting sort of edges by center: count -> scan -> place
// ---------------------------------------------------------------------------
__global__ void k_count(const int* __restrict__ centers) {
    int i = blockIdx.x * blockDim.x + threadIdx.x;
    if (i < N_EDGES) atomicAdd(&g_cnt[__ldg(&centers[i])], 1);
}

__global__ __launch_bounds__(1024) void k_scan() {
    __shared__ int s[1024];
    const int t = threadIdx.x;
    const int base = t * 10;             // 1024*10 >= N_ATOMS
    int loc[10], sum = 0;
    #pragma unroll
    for (int i = 0; i < 10; i++) {
        int idx = base + i;
        int v = (idx < N_ATOMS) ? g_cnt[idx] : 0;
        loc[i] = sum; sum += v;
    }
    s[t] = sum;
    __syncthreads();
    for (int d = 1; d < 1024; d <<= 1) {
        int v = (t >= d) ? s[t - d] : 0;
        __syncthreads();
        s[t] += v;
        __syncthreads();
    }
    int excl = (t == 0) ? 0 : s[t - 1];
    #pragma unroll
    for (int i = 0; i < 10; i++) {
        int idx = base + i;
        if (idx < N_ATOMS) {
            int o = excl + loc[i];
            g_off[idx] = o;
            g_cur[idx] = o;
        }
    }
    if (t == 1023) g_off[N_ATOMS] = excl + sum;
}

__global__ void k_place(const int* __restrict__ centers) {
    int i = blockIdx.x * blockDim.x + threadIdx.x;
    if (i < N_EDGES) {
        int slot = atomicAdd(&g_cur[__ldg(&centers[i])], 1);
        g_eid[slot] = i;
    }
}

// ---------------------------------------------------------------------------
// K_pool: one block per atom. Iterate this atom's edges (sorted), compute
// per-edge radial + coupling coefficients in smem, gather uncF[neighbor],
// accumulate 1280 channels in registers (10/thread), single plain store.
// NO global atomics.
// ---------------------------------------------------------------------------
__global__ __launch_bounds__(128) void k_pool(
    const float* __restrict__ r,
    const float* __restrict__ sh0, const float* __restrict__ sh1,
    const float* __restrict__ sh2, const float* __restrict__ sh3,
    const float* __restrict__ Wr0, const float* __restrict__ Wr1,
    const float* __restrict__ Wr2, const float* __restrict__ Wr3,
    const float* __restrict__ U0, const float* __restrict__ U1,
    const float* __restrict__ U2, const float* __restrict__ U3,
    const int* __restrict__ neighbors)
{
    __shared__ float s_sh[16];
    __shared__ float s_rb[8];
    __shared__ float s_rad[320];   // radial rows: offsets {0,128,224,288}
    __shared__ float s_cc[144];    // c_l[d,lp]: offsets {0,1,7,34}, 142 used

    const int n = blockIdx.x;
    const int t = threadIdx.x;
    const int e0 = g_off[n];
    const int e1 = g_off[n + 1];

    // per-thread channel metadata (channels c = t + 128*j)
    int lj[10], ccb[10], lok[10];
    #pragma unroll
    for (int j = 0; j < 10; j++) {
        int c   = t + 128 * j;
        int l   = (c >= 416) ? 3 : (c >= 128) ? 2 : (c >= 32) ? 1 : 0;
        int idx = c - sel4(l, 0, 32, 128, 416);
        int d   = idx >> 5;
        int k   = idx & 31;
        lj[j]  = l;
        ccb[j] = sel4(l, 0, 1, 7, 34) + d * (l + 1);
        lok[j] = sel4(l, 96, 64, 32, 0) + k;
    }

    float acc[10];
    #pragma unroll
    for (int j = 0; j < 10; j++) acc[j] = 0.f;

    for (int ei = e0; ei < e1; ei++) {
        const int e = g_eid[ei];

        if (t < 16) {
            float v;
            if (t == 0)      v = __ldg(&sh0[e]);
            else if (t < 4)  v = __ldg(&sh1[(size_t)e * 3 + (t - 1)]);
            else if (t < 9)  v = __ldg(&sh2[(size_t)e * 5 + (t - 4)]);
            else             v = __ldg(&sh3[(size_t)e * 7 + (t - 9)]);
            s_sh[t] = v;
        } else if (t < 24) {
            int lane = t - 16;
            const float PI = 3.14159265358979323846f;
            float rv = __ldg(&r[e]);
            float fc = 0.5f * (cosf(PI * fminf(rv * 0.2f, 1.0f)) + 1.0f);
            float a  = rv * (PI * 0.2f);
            s_rb[lane] = sinf((float)(lane + 1) * a) / (rv + 1e-6f) * fc;
        }
        __syncthreads();

        // radial[lp][c] = rb . Wrad_lp[:,c]   (320 values)
        for (int q = t; q < 320; q += 128) {
            int lp = (q >= 288) ? 3 : (q >= 224) ? 2 : (q >= 128) ? 1 : 0;
            int c  = q - sel4(lp, 0, 128, 224, 288);
            int w  = sel4(lp, 128, 96, 64, 32);
            const float* W = selp(lp, Wr0, Wr1, Wr2, Wr3);
            float a = 0.f;
            #pragma unroll
            for (int i = 0; i < 8; i++)
                a += s_rb[i] * __ldg(&W[i * w + c]);
            s_rad[q] = a;
        }
        // c_l[d,lp] = sum_m U_l[d, lp^2+m] * sh_lp[m]   (142 values)
        for (int q = t; q < 142; q += 128) {
            int l   = (q >= 34) ? 3 : (q >= 7) ? 2 : (q >= 1) ? 1 : 0;
            int rem = q - sel4(l, 0, 1, 7, 34);
            int d   = rem / (l + 1);
            int lp  = rem - d * (l + 1);
            const float* Ul = selp(l, U0, U1, U2, U3);
            int ubase = d * (l + 1) * (l + 1) + lp * lp;
            int shoff = lp * lp;
            float a = 0.f;
            int ub = 2 * lp + 1;
            for (int m = 0; m < ub; m++)
                a += __ldg(&Ul[ubase + m]) * s_sh[shoff + m];
            s_cc[q] = a;
        }
        __syncthreads();

        const int nb = __ldg(&neighbors[e]);
        const float* fN = g_uncF + (size_t)nb * UNC_W;
        #pragma unroll
        for (int j = 0; j < 10; j++) {
            float coef = 0.f;
            int l = lj[j];
            #pragma unroll
            for (int lp = 0; lp <= 3; lp++) {
                if (lp > l) break;
                coef += s_cc[ccb[j] + lp] * s_rad[sel4(lp, 0, 128, 224, 288) + lok[j]];
            }
            acc[j] += coef * __ldg(&fN[t + 128 * j]);
        }
        // barrier at loop top (via next iteration's first sync) protects s_rad;
        // but next iter writes s_sh before that sync -> s_sh unused in acc loop, safe.
    }

    float* dst = g_pool + (size_t)n * UNC_W;
    #pragma unroll
    for (int j = 0; j < 10; j++) dst[t + 128 * j] = acc[j];
}

// ---------------------------------------------------------------------------
// K_couple: couple pooled back into cat layout -> g_cat.
// ---------------------------------------------------------------------------
__global__ __launch_bounds__(128) void k_couple(
    const float* __restrict__ U0, const float* __restrict__ U1,
    const float* __restrict__ U2, const float* __restrict__ U3)
{
    __shared__ float pb[UNC_W];
    const int n = blockIdx.x;
    const int t = threadIdx.x;

    {
        const float4* src = reinterpret_cast<const float4*>(g_pool + (size_t)n * UNC_W);
        for (int u = t; u < UNC_W / 4; u += 128)
            reinterpret_cast<float4*>(pb)[u] = src[u];
    }
    __syncthreads();

    float* dst = g_cat + (size_t)n * CAT_W;
    for (int v = t; v < CAT_W; v += 128) {
        int lp  = (v >= 448) ? 3 : (v >= 160) ? 2 : (v >= 32) ? 1 : 0;
        int rem = v - sel4(lp, 0, 32, 160, 448);
        int mm  = rem >> 5;
        int k   = rem & 31;
        const float* Ul = selp(lp, U0, U1, U2, U3);
        int L1 = (lp + 1) * (lp + 1);
        int D  = sel4(lp, 1, 3, 9, 27);
        int pof = sel4(lp, 0, 32, 128, 416);
        float acc = 0.f;
        for (int d = 0; d < D; d++)
            acc += __ldg(&Ul[d * L1 + mm]) * pb[pof + d * 32 + k];
        int l = (mm >= 9) ? 3 : (mm >= 4) ? 2 : (mm >= 1) ? 1 : 0;
        int m = mm - l * l;
        int K = sel4(l, 128, 96, 64, 32);
        dst[sel4(l, 0, 128, 416, 736) + m * K + (lp - l) * 32 + k] = acc;
    }
}

// ---------------------------------------------------------------------------
// Unified GEMM: out_l = feat_l + cat_l @ Wlin_l for all l in ONE launch.
// Register-blocked body: BM=64, BN=K, BK=16, 256 threads, 4 x (K/16) accs.
// ---------------------------------------------------------------------------
template<int K, int NR, int OFF_CAT, size_t OFF_OUT>
__device__ __forceinline__ void gemm_body(
    int bid, const float* __restrict__ W, const float* __restrict__ feat,
    float* __restrict__ out, float* As, float* Bs)
{
    constexpr int BM = 64, BK = 16, LDA = BM + 1;
    constexpr int TN = K / 16;             // cols per thread (8,6,4,2)

    const int t    = threadIdx.x;
    const int trow = t >> 4;
    const int tcol = t & 15;
    const int row0 = bid * BM;

    float acc[4][TN];
    #pragma unroll
    for (int i = 0; i < 4; i++)
        #pragma unroll
        for (int j = 0; j < TN; j++) acc[i][j] = 0.f;

    const int ra = t >> 2;
    const int ca = t & 3;
    const int grow = row0 + ra;
    const int atomA = grow / NR;
    const int mA    = grow - atomA * NR;
    const float* arow = (atomA < N_ATOMS)
        ? g_cat + (size_t)atomA * CAT_W + OFF_CAT + mA * K
        : nullptr;

    for (int k0 = 0; k0 < K; k0 += BK) {
        {
            float4 v = make_float4(0.f, 0.f, 0.f, 0.f);
            if (arow) v = *reinterpret_cast<const float4*>(arow + k0 + ca * 4);
            As[(ca * 4 + 0) * LDA + ra] = v.x;
            As[(ca * 4 + 1) * LDA + ra] = v.y;
            As[(ca * 4 + 2) * LDA + ra] = v.z;
            As[(ca * 4 + 3) * LDA + ra] = v.w;
        }
        {
            constexpr int T4 = BK * K / 4;
            #pragma unroll
            for (int i = t; i < T4; i += 256) {
                int br = i / (K / 4);
                int bc = i - br * (K / 4);
                *reinterpret_cast<float4*>(&Bs[br * K + bc * 4]) =
                    __ldg(reinterpret_cast<const float4*>(&W[(k0 + br) * K + bc * 4]));
            }
        }
        __syncthreads();

        #pragma unroll
        for (int kk = 0; kk < BK; kk++) {
            float a0 = As[kk * LDA + trow * 4 + 0];
            float a1 = As[kk * LDA + trow * 4 + 1];
            float a2 = As[kk * LDA + trow * 4 + 2];
            float a3 = As[kk * LDA + trow * 4 + 3];
            #pragma unroll
            for (int j = 0; j < TN; j++) {
                float b = Bs[kk * K + tcol * TN + j];
                acc[0][j] += a0 * b;
                acc[1][j] += a1 * b;
                acc[2][j] += a2 * b;
                acc[3][j] += a3 * b;
            }
        }
        __syncthreads();
    }

    #pragma unroll
    for (int i = 0; i < 4; i++) {
        int grow2 = row0 + trow * 4 + i;
        int atom  = grow2 / NR;
        int m     = grow2 - atom * NR;
        if (atom >= N_ATOMS) continue;
        size_t base = (size_t)atom * NR * K + m * K + tcol * TN;
        const float* fr = feat + base;
        float*       op = out + OFF_OUT + base;
        #pragma unroll
        for (int j = 0; j < TN; j++)
            op[j] = acc[i][j] + __ldg(&fr[j]);
    }
}

#define NB0 157   // ceil(10000*1/64)
#define NB1 469   // ceil(10000*3/64)
#define NB2 782   // ceil(10000*5/64)
#define NB3 1094  // ceil(10000*7/64)

__global__ __launch_bounds__(256) void k_gemm_all(
    const float* __restrict__ W0, const float* __restrict__ W1,
    const float* __restrict__ W2, const float* __restrict__ W3,
    const float* __restrict__ f0, const float* __restrict__ f1,
    const float* __restrict__ f2, const float* __restrict__ f3,
    float* __restrict__ out)
{
    __shared__ float As[16 * 65];
    __shared__ float Bs[16 * 128];
    const int b = blockIdx.x;
    if (b < NB0)
        gemm_body<128, 1,   0, (size_t)0      >(b, W0, f0, out, As, Bs);
    else if (b < NB0 + NB1)
        gemm_body< 96, 3, 128, (size_t)1280000>(b - NB0, W1, f1, out, As, Bs);
    else if (b < NB0 + NB1 + NB2)
        gemm_body< 64, 5, 416, (size_t)4160000>(b - NB0 - NB1, W2, f2, out, As, Bs);
    else
        gemm_body< 32, 7, 736, (size_t)7360000>(b - NB0 - NB1 - NB2, W3, f3, out, As, Bs);
}

// ---------------------------------------------------------------------------
// kernel_launch: robust input binding (detect metadata ordering via in_sizes).
// ---------------------------------------------------------------------------
extern "C" void kernel_launch(void* const* d_in, const int* in_sizes, int n_in,
                              void* d_out, int out_size)
{
    int I_r, I_sh[4], I_f[4], I_Wr[4], I_U[4], I_Wl[4], I_c, I_nb;

    if (in_sizes[0] == 1) {
        for (int l = 0; l < 4; l++) { I_U[l] = l; I_Wl[l] = 4 + l; I_Wr[l] = 8 + l; }
        I_c = 12;
        for (int l = 0; l < 4; l++) I_f[l] = 13 + l;
        I_nb = 17; I_r = 18;
        for (int l = 0; l < 4; l++) I_sh[l] = 19 + l;
    } else if (in_sizes[2] == 1280000) {
        I_r = 0;
        for (int l = 0; l < 4; l++) {
            I_sh[l] = 1 + 5 * l; I_f[l]  = 2 + 5 * l; I_Wr[l] = 3 + 5 * l;
            I_U[l]  = 4 + 5 * l; I_Wl[l] = 5 + 5 * l;
        }
        I_c = 21; I_nb = 22;
    } else {
        I_r = 0;
        for (int l = 0; l < 4; l++) {
            I_sh[l] = 1 + l; I_f[l] = 5 + l; I_Wr[l] = 9 + l;
            I_U[l] = 13 + l; I_Wl[l] = 17 + l;
        }
        I_c = 21; I_nb = 22;
    }

    const float* r   = (const float*)d_in[I_r];
    const float* sh0 = (const float*)d_in[I_sh[0]];
    const float* sh1 = (const float*)d_in[I_sh[1]];
    const float* sh2 = (const float*)d_in[I_sh[2]];
    const float* sh3 = (const float*)d_in[I_sh[3]];
    const float* f0  = (const float*)d_in[I_f[0]];
    const float* f1  = (const float*)d_in[I_f[1]];
    const float* f2  = (const float*)d_in[I_f[2]];
    const float* f3  = (const float*)d_in[I_f[3]];
    const float* Wr0 = (const float*)d_in[I_Wr[0]];
    const float* Wr1 = (const float*)d_in[I_Wr[1]];
    const float* Wr2 = (const float*)d_in[I_Wr[2]];
    const float* Wr3 = (const float*)d_in[I_Wr[3]];
    const float* U0  = (const float*)d_in[I_U[0]];
    const float* U1  = (const float*)d_in[I_U[1]];
    const float* U2  = (const float*)d_in[I_U[2]];
    const float* U3  = (const float*)d_in[I_U[3]];
    const float* W0  = (const float*)d_in[I_Wl[0]];
    const float* W1  = (const float*)d_in[I_Wl[1]];
    const float* W2  = (const float*)d_in[I_Wl[2]];
    const float* W3  = (const float*)d_in[I_Wl[3]];
    const int* centers   = (const int*)d_in[I_c];
    const int* neighbors = (const int*)d_in[I_nb];
    float* out = (float*)d_out;

    k_uncf<<<N_ATOMS, 128>>>(f0, f1, f2, f3, U0, U1, U2, U3);   // + cnt zero
    k_count<<<(N_EDGES + 255) / 256, 256>>>(centers);
    k_scan<<<1, 1024>>>();
    k_place<<<(N_EDGES + 255) / 256, 256>>>(centers);
    k_pool<<<N_ATOMS, 128>>>(r, sh0, sh1, sh2, sh3,
                             Wr0, Wr1, Wr2, Wr3,
                             U0, U1, U2, U3, neighbors);
    k_couple<<<N_ATOMS, 128>>>(U0, U1, U2, U3);
    k_gemm_all<<<NB0 + NB1 + NB2 + NB3, 256>>>(W0, W1, W2, W3,
                                               f0, f1, f2, f3, out);
}

// round 13
// speedup vs baseline: 1.2525x; 1.2525x over previous
#include <cuda_runtime.h>
#include <math.h>

#define N_EDGES 100000
#define N_ATOMS 10000
#define UNC_W   1280   // sum over l of 3^l * 32 = 32+96+288+864
#define CAT_W   960

// uncoupled-space per-atom features and pooled scatter target (both ~51.2MB, L2-resident)
__device__ __align__(16) float g_uncF[(size_t)N_ATOMS * UNC_W];
__device__ __align__(16) float g_pool[(size_t)N_ATOMS * UNC_W];
// cat scratch reuses g_uncF (k_edge has finished reading it before k_couple writes)
#define g_cat g_uncF

// ---------------------------------------------------------------------------
// helpers (branchless select chains; avoid local-memory arrays)
// ---------------------------------------------------------------------------
__device__ __forceinline__ int sel4(int l, int a, int b, int c, int d) {
    return l == 0 ? a : (l == 1 ? b : (l == 2 ? c : d));
}
__device__ __forceinline__ const float* selp(int l, const float* a, const float* b,
                                             const float* c, const float* d) {
    return l == 0 ? a : (l == 1 ? b : (l == 2 ? c : d));
}

__device__ __forceinline__ void red_add_v4(float* addr, float x, float y, float z, float w) {
    asm volatile("red.global.add.v4.f32 [%0], {%1,%2,%3,%4};"
                 :: "l"(addr), "f"(x), "f"(y), "f"(z), "f"(w) : "memory");
}

// ---------------------------------------------------------------------------
// K_uncF: per-atom uncouple of features (+ fused zeroing of g_pool row).
// unc_f[l][d,k] = sum_{lp<=l} sum_m U_l[d, lp^2+m] * feat_lp[n, m, lo_l + k]
// layout: g_uncF[n*1280 + F_OFF[l] + d*32 + k], F_OFF={0,32,128,416}
// ---------------------------------------------------------------------------
__global__ __launch_bounds__(128) void k_uncf(
    const float* __restrict__ f0, const float* __restrict__ f1,
    const float* __restrict__ f2, const float* __restrict__ f3,
    const float* __restrict__ U0, const float* __restrict__ U1,
    const float* __restrict__ U2, const float* __restrict__ U3)
{
    __shared__ float fb[CAT_W];  // all feat rows of this atom: offsets {0,128,416,736}
    const int n = blockIdx.x;
    const int t = threadIdx.x;

    // fused: zero this atom's pooled accumulator row (320 float4 = 1280 floats)
    {
        float4 z = make_float4(0.f, 0.f, 0.f, 0.f);
        float4* pz = reinterpret_cast<float4*>(g_pool + (size_t)n * UNC_W);
        for (int u = t; u < UNC_W / 4; u += 128) pz[u] = z;
    }

    // cooperative float4 copy of feat[n] (sizes 128,288,320,224 floats)
    for (int u = t; u < 240; u += 128) {
        int l    = (u >= 184) ? 3 : (u >= 104) ? 2 : (u >= 32) ? 1 : 0;
        int off4 = u - sel4(l, 0, 32, 104, 184);
        int row  = sel4(l, 128, 288, 320, 224);
        const float* src = selp(l, f0, f1, f2, f3) + (size_t)n * row;
        float4 v = __ldg(reinterpret_cast<const float4*>(src + off4 * 4));
        *reinterpret_cast<float4*>(&fb[sel4(l, 0, 128, 416, 736) + off4 * 4]) = v;
    }
    __syncthreads();

    float* dst = g_uncF + (size_t)n * UNC_W;
    for (int v = t; v < UNC_W; v += 128) {
        int l   = (v >= 416) ? 3 : (v >= 128) ? 2 : (v >= 32) ? 1 : 0;
        int idx = v - sel4(l, 0, 32, 128, 416);
        int d   = idx >> 5;
        int k   = idx & 31;
        int lo  = sel4(l, 96, 64, 32, 0);
        const float* Ul = selp(l, U0, U1, U2, U3);
        int L1 = (l + 1) * (l + 1);
        float acc = 0.f;
        #pragma unroll
        for (int lp = 0; lp <= 3; lp++) {
            if (lp > l) break;
            int fboff = sel4(lp, 0, 128, 416, 736);
            int w     = sel4(lp, 128, 96, 64, 32);
            int ub    = 2 * lp + 1;
            int ubase = d * L1 + lp * lp;
            for (int m = 0; m < ub; m++)
                acc += __ldg(&Ul[ubase + m]) * fb[fboff + m * w + lo + k];
        }
        dst[v] = acc;
    }
}

// ---------------------------------------------------------------------------
// K_edge: fused radial + coupling coefficients + gather + multiply + scatter.
// One warp per edge, 8 warps/block. (Measured-best pooling path.)
// ---------------------------------------------------------------------------
__global__ __launch_bounds__(256) void k_edge(
    const float* __restrict__ r,
    const float* __restrict__ sh0, const float* __restrict__ sh1,
    const float* __restrict__ sh2, const float* __restrict__ sh3,
    const float* __restrict__ Wr0, const float* __restrict__ Wr1,
    const float* __restrict__ Wr2, const float* __restrict__ Wr3,
    const float* __restrict__ U0, const float* __restrict__ U1,
    const float* __restrict__ U2, const float* __restrict__ U3,
    const int* __restrict__ centers, const int* __restrict__ neighbors)
{
    __shared__ float s_sh[8][16];
    __shared__ float s_rb[8][8];
    __shared__ float s_rad[8][320];   // radial_lp full rows: offsets {0,128,224,288}
    __shared__ float s_cc[8][144];    // c_l[d,lp] coeffs: offsets {0,1,7,34}, 142 used

    const int wid  = threadIdx.x >> 5;
    const int lane = threadIdx.x & 31;
    const int e    = blockIdx.x * 8 + wid;
    if (e >= N_EDGES) return;

    const float rv = __ldg(&r[e]);

    // spherical-harmonic values for this edge (16 floats)
    if (lane < 16) {
        float v;
        if (lane == 0)      v = __ldg(&sh0[e]);
        else if (lane < 4)  v = __ldg(&sh1[(size_t)e * 3 + (lane - 1)]);
        else if (lane < 9)  v = __ldg(&sh2[(size_t)e * 5 + (lane - 4)]);
        else                v = __ldg(&sh3[(size_t)e * 7 + (lane - 9)]);
        s_sh[wid][lane] = v;
    }
    // radial basis (8 values) with smooth cutoff
    if (lane < 8) {
        const float PI = 3.14159265358979323846f;
        float fc = 0.5f * (cosf(PI * fminf(rv * 0.2f, 1.0f)) + 1.0f);
        float a  = rv * (PI * 0.2f);
        s_rb[wid][lane] = sinf((float)(lane + 1) * a) / (rv + 1e-6f) * fc;
    }
    __syncwarp();

    // radial[lp][c] = rb . Wrad_lp[:,c], all 320 values
    for (int t = lane; t < 320; t += 32) {
        int lp = (t >= 288) ? 3 : (t >= 224) ? 2 : (t >= 128) ? 1 : 0;
        int c  = t - sel4(lp, 0, 128, 224, 288);
        int w  = sel4(lp, 128, 96, 64, 32);
        const float* W = selp(lp, Wr0, Wr1, Wr2, Wr3);
        float acc = 0.f;
        #pragma unroll
        for (int i = 0; i < 8; i++)
            acc += s_rb[wid][i] * __ldg(&W[i * w + c]);
        s_rad[wid][t] = acc;
    }
    // c_l[d,lp] = sum_m U_l[d, lp^2+m] * sh_lp[m]   (142 values)
    for (int t = lane; t < 142; t += 32) {
        int l   = (t >= 34) ? 3 : (t >= 7) ? 2 : (t >= 1) ? 1 : 0;
        int rem = t - sel4(l, 0, 1, 7, 34);
        int d   = rem / (l + 1);
        int lp  = rem - d * (l + 1);
        const float* Ul = selp(l, U0, U1, U2, U3);
        int ubase = d * (l + 1) * (l + 1) + lp * lp;
        int shoff = lp * lp;   // {0,1,4,9}
        float acc = 0.f;
        int ub = 2 * lp + 1;
        for (int m = 0; m < ub; m++)
            acc += __ldg(&Ul[ubase + m]) * s_sh[wid][shoff + m];
        s_cc[wid][t] = acc;
    }
    __syncwarp();

    const int ctr = __ldg(&centers[e]);
    const int nb  = __ldg(&neighbors[e]);
    const float* fN = g_uncF + (size_t)nb  * UNC_W;
    float*       pC = g_pool + (size_t)ctr * UNC_W;

    #pragma unroll
    for (int j = 0; j < 10; j++) {
        int u  = lane + 32 * j;
        int cbc = u * 4;
        int l  = (cbc >= 416) ? 3 : (cbc >= 128) ? 2 : (cbc >= 32) ? 1 : 0;
        int idx = cbc - sel4(l, 0, 32, 128, 416);
        int d   = idx >> 5;
        int k0  = idx & 31;
        int lo  = sel4(l, 96, 64, 32, 0);

        float4 f4 = __ldg(reinterpret_cast<const float4*>(fN + cbc));

        float u0 = 0.f, u1 = 0.f, u2 = 0.f, u3 = 0.f;
        const float* ccp = &s_cc[wid][sel4(l, 0, 1, 7, 34) + d * (l + 1)];
        #pragma unroll
        for (int lp = 0; lp <= 3; lp++) {
            if (lp > l) break;
            float c = ccp[lp];
            const float* rp = &s_rad[wid][sel4(lp, 0, 128, 224, 288) + lo + k0];
            u0 += c * rp[0]; u1 += c * rp[1]; u2 += c * rp[2]; u3 += c * rp[3];
        }
        red_add_v4(pC + cbc, u0 * f4.x, u1 * f4.y, u2 * f4.z, u3 * f4.w);
    }
}

// ---------------------------------------------------------------------------
// K_couple: couple pooled back into cat layout, write to g_cat (global).
// cat layout per atom (960 floats): offsets {0,128,416,736}, row width KMAX[l],
// entry [l][m][ (lp-l)*32 + k ].
// ---------------------------------------------------------------------------
__global__ __launch_bounds__(128) void k_couple(
    const float* __restrict__ U0, const float* __restrict__ U1,
    const float* __restrict__ U2, const float* __restrict__ U3)
{
    __shared__ float pb[UNC_W];
    const int n = blockIdx.x;
    const int t = threadIdx.x;

    {
        const float4* src = reinterpret_cast<const float4*>(g_pool + (size_t)n * UNC_W);
        for (int u = t; u < UNC_W / 4; u += 128)
            reinterpret_cast<float4*>(pb)[u] = src[u];
    }
    __syncthreads();

    float* dst = g_cat + (size_t)n * CAT_W;
    for (int v = t; v < CAT_W; v += 128) {
        int lp  = (v >= 448) ? 3 : (v >= 160) ? 2 : (v >= 32) ? 1 : 0;
        int rem = v - sel4(lp, 0, 32, 160, 448);
        int mm  = rem >> 5;
        int k   = rem & 31;
        const float* Ul = selp(lp, U0, U1, U2, U3);
        int L1 = (lp + 1) * (lp + 1);
        int D  = sel4(lp, 1, 3, 9, 27);
        int pof = sel4(lp, 0, 32, 128, 416);
        float acc = 0.f;
        for (int d = 0; d < D; d++)
            acc += __ldg(&Ul[d * L1 + mm]) * pb[pof + d * 32 + k];
        int l = (mm >= 9) ? 3 : (mm >= 4) ? 2 : (mm >= 1) ? 1 : 0;
        int m = mm - l * l;
        int K = sel4(l, 128, 96, 64, 32);
        dst[sel4(l, 0, 128, 416, 736) + m * K + (lp - l) * 32 + k] = acc;
    }
}

// ---------------------------------------------------------------------------
// Unified GEMM: out_l = feat_l + cat_l @ Wlin_l for all l in ONE launch.
// Register-blocked body: BM=64, BN=K, BK=16, 256 threads, 4 x (K/16) accs.
// ---------------------------------------------------------------------------
template<int K, int NR, int OFF_CAT, size_t OFF_OUT>
__device__ __forceinline__ void gemm_body(
    int bid, const float* __restrict__ W, const float* __restrict__ feat,
    float* __restrict__ out, float* As, float* Bs)
{
    constexpr int BM = 64, BK = 16, LDA = BM + 1;
    constexpr int TN = K / 16;             // cols per thread (8,6,4,2)

    const int t    = threadIdx.x;
    const int trow = t >> 4;
    const int tcol = t & 15;
    const int row0 = bid * BM;

    float acc[4][TN];
    #pragma unroll
    for (int i = 0; i < 4; i++)
        #pragma unroll
        for (int j = 0; j < TN; j++) acc[i][j] = 0.f;

    const int ra = t >> 2;
    const int ca = t & 3;
    const int grow = row0 + ra;
    const int atomA = grow / NR;
    const int mA    = grow - atomA * NR;
    const float* arow = (atomA < N_ATOMS)
        ? g_cat + (size_t)atomA * CAT_W + OFF_CAT + mA * K
        : nullptr;

    for (int k0 = 0; k0 < K; k0 += BK) {
        {
            float4 v = make_float4(0.f, 0.f, 0.f, 0.f);
            if (arow) v = *reinterpret_cast<const float4*>(arow + k0 + ca * 4);
            As[(ca * 4 + 0) * LDA + ra] = v.x;
            As[(ca * 4 + 1) * LDA + ra] = v.y;
            As[(ca * 4 + 2) * LDA + ra] = v.z;
            As[(ca * 4 + 3) * LDA + ra] = v.w;
        }
        {
            constexpr int T4 = BK * K / 4;
            #pragma unroll
            for (int i = t; i < T4; i += 256) {
                int br = i / (K / 4);
                int bc = i - br * (K / 4);
                *reinterpret_cast<float4*>(&Bs[br * K + bc * 4]) =
                    __ldg(reinterpret_cast<const float4*>(&W[(k0 + br) * K + bc * 4]));
            }
        }
        __syncthreads();

        #pragma unroll
        for (int kk = 0; kk < BK; kk++) {
            float a0 = As[kk * LDA + trow * 4 + 0];
            float a1 = As[kk * LDA + trow * 4 + 1];
            float a2 = As[kk * LDA + trow * 4 + 2];
            float a3 = As[kk * LDA + trow * 4 + 3];
            #pragma unroll
            for (int j = 0; j < TN; j++) {
                float b = Bs[kk * K + tcol * TN + j];
                acc[0][j] += a0 * b;
                acc[1][j] += a1 * b;
                acc[2][j] += a2 * b;
                acc[3][j] += a3 * b;
            }
        }
        __syncthreads();
    }

    #pragma unroll
    for (int i = 0; i < 4; i++) {
        int grow2 = row0 + trow * 4 + i;
        int atom  = grow2 / NR;
        int m     = grow2 - atom * NR;
        if (atom >= N_ATOMS) continue;
        size_t base = (size_t)atom * NR * K + m * K + tcol * TN;
        const float* fr = feat + base;
        float*       op = out + OFF_OUT + base;
        #pragma unroll
        for (int j = 0; j < TN; j++)
            op[j] = acc[i][j] + __ldg(&fr[j]);
    }
}

#define NB0 157   // ceil(10000*1/64)
#define NB1 469   // ceil(10000*3/64)
#define NB2 782   // ceil(10000*5/64)
#define NB3 1094  // ceil(10000*7/64)

__global__ __launch_bounds__(256) void k_gemm_all(
    const float* __restrict__ W0, const float* __restrict__ W1,
    const float* __restrict__ W2, const float* __restrict__ W3,
    const float* __restrict__ f0, const float* __restrict__ f1,
    const float* __restrict__ f2, const float* __restrict__ f3,
    float* __restrict__ out)
{
    __shared__ float As[16 * 65];
    __shared__ float Bs[16 * 128];
    const int b = blockIdx.x;
    if (b < NB0)
        gemm_body<128, 1,   0, (size_t)0      >(b, W0, f0, out, As, Bs);
    else if (b < NB0 + NB1)
        gemm_body< 96, 3, 128, (size_t)1280000>(b - NB0, W1, f1, out, As, Bs);
    else if (b < NB0 + NB1 + NB2)
        gemm_body< 64, 5, 416, (size_t)4160000>(b - NB0 - NB1, W2, f2, out, As, Bs);
    else
        gemm_body< 32, 7, 736, (size_t)7360000>(b - NB0 - NB1 - NB2, W3, f3, out, As, Bs);
}

// ---------------------------------------------------------------------------
// kernel_launch: robust input binding (detect metadata ordering via in_sizes).
// ---------------------------------------------------------------------------
extern "C" void kernel_launch(void* const* d_in, const int* in_sizes, int n_in,
                              void* d_out, int out_size)
{
    int I_r, I_sh[4], I_f[4], I_Wr[4], I_U[4], I_Wl[4], I_c, I_nb;

    if (in_sizes[0] == 1) {
        for (int l = 0; l < 4; l++) { I_U[l] = l; I_Wl[l] = 4 + l; I_Wr[l] = 8 + l; }
        I_c = 12;
        for (int l = 0; l < 4; l++) I_f[l] = 13 + l;
        I_nb = 17; I_r = 18;
        for (int l = 0; l < 4; l++) I_sh[l] = 19 + l;
    } else if (in_sizes[2] == 1280000) {
        I_r = 0;
        for (int l = 0; l < 4; l++) {
            I_sh[l] = 1 + 5 * l; I_f[l]  = 2 + 5 * l; I_Wr[l] = 3 + 5 * l;
            I_U[l]  = 4 + 5 * l; I_Wl[l] = 5 + 5 * l;
        }
        I_c = 21; I_nb = 22;
    } else {
        I_r = 0;
        for (int l = 0; l < 4; l++) {
            I_sh[l] = 1 + l; I_f[l] = 5 + l; I_Wr[l] = 9 + l;
            I_U[l] = 13 + l; I_Wl[l] = 17 + l;
        }
        I_c = 21; I_nb = 22;
    }

    const float* r   = (const float*)d_in[I_r];
    const float* sh0 = (const float*)d_in[I_sh[0]];
    const float* sh1 = (const float*)d_in[I_sh[1]];
    const float* sh2 = (const float*)d_in[I_sh[2]];
    const float* sh3 = (const float*)d_in[I_sh[3]];
    const float* f0  = (const float*)d_in[I_f[0]];
    const float* f1  = (const float*)d_in[I_f[1]];
    const float* f2  = (const float*)d_in[I_f[2]];
    const float* f3  = (const float*)d_in[I_f[3]];
    const float* Wr0 = (const float*)d_in[I_Wr[0]];
    const float* Wr1 = (const float*)d_in[I_Wr[1]];
    const float* Wr2 = (const float*)d_in[I_Wr[2]];
    const float* Wr3 = (const float*)d_in[I_Wr[3]];
    const float* U0  = (const float*)d_in[I_U[0]];
    const float* U1  = (const float*)d_in[I_U[1]];
    const float* U2  = (const float*)d_in[I_U[2]];
    const float* U3  = (const float*)d_in[I_U[3]];
    const float* W0  = (const float*)d_in[I_Wl[0]];
    const float* W1  = (const float*)d_in[I_Wl[1]];
    const float* W2  = (const float*)d_in[I_Wl[2]];
    const float* W3  = (const float*)d_in[I_Wl[3]];
    const int* centers   = (const int*)d_in[I_c];
    const int* neighbors = (const int*)d_in[I_nb];
    float* out = (float*)d_out;

    k_uncf<<<N_ATOMS, 128>>>(f0, f1, f2, f3, U0, U1, U2, U3);   // + pool zero
    k_edge<<<(N_EDGES + 7) / 8, 256>>>(r, sh0, sh1, sh2, sh3,
                                       Wr0, Wr1, Wr2, Wr3,
                                       U0, U1, U2, U3, centers, neighbors);
    k_couple<<<N_ATOMS, 128>>>(U0, U1, U2, U3);
    k_gemm_all<<<NB0 + NB1 + NB2 + NB3, 256>>>(W0, W1, W2, W3,
                                               f0, f1, f2, f3, out);
}